// round 4
// baseline (speedup 1.0000x reference)
#include <cuda_runtime.h>
#include <math.h>

// ---------------- device scratch (no allocations allowed) ----------------
// Transposed input: (b, d, t) layout, contiguous along t. 16*256*4096 fp32 = 64MB.
__device__ float  g_xt[16u * 256u * 4096u];
// Per-signal selected coefficients: 4096 signals * 7 entries of (amp, phase, k, pad)
__device__ float4 g_sel[4096 * 7];

#define NSIG   4096      // 16 * 256 signals
#define TLEN   4096      // time length
#define NHALF  2048      // complex FFT length (real-packed)
#define KTOP   7         // int(ln(2047)) = 7

// ---------------- kernel 1: transpose (b,t,d) -> (b,d,t) ----------------
__global__ void transpose_kernel(const float* __restrict__ in) {
    __shared__ float tile[32][33];
    int b  = blockIdx.z;
    int t0 = blockIdx.x * 32;
    int d0 = blockIdx.y * 32;
    const float* inp = in + (size_t)b * TLEN * 256;
#pragma unroll
    for (int k = 0; k < 4; k++) {
        int tl = threadIdx.y + k * 8;
        tile[tl][threadIdx.x] = inp[(size_t)(t0 + tl) * 256 + d0 + threadIdx.x];
    }
    __syncthreads();
    float* outp = g_xt + (size_t)b * 256 * TLEN;
#pragma unroll
    for (int k = 0; k < 4; k++) {
        int dl = threadIdx.y + k * 8;
        outp[(size_t)(d0 + dl) * TLEN + t0 + threadIdx.x] = tile[threadIdx.x][dl];
    }
}

// ---------------- kernel 2: per-signal 2048-pt Stockham FFT + top-7 ------
__global__ void __launch_bounds__(256) fft_topk_kernel() {
    __shared__ float2 bufA[NHALF];
    __shared__ float2 bufB[NHALF];
    __shared__ float2 tw[1024];                  // e^{-i*pi*m/1024}, m=0..1023
    __shared__ unsigned long long red[8];
    __shared__ int winners[KTOP];

    const int tid = threadIdx.x;
    const int s   = blockIdx.x;                  // signal id = b*256 + d

    // load packed real signal: z[n] = x[2n] + i*x[2n+1]
    const float2* zin = (const float2*)(g_xt + (size_t)s * TLEN);
    for (int i = tid; i < NHALF; i += 256) bufA[i] = zin[i];
    for (int m = tid; m < 1024; m += 256) {
        float sv, cv;
        sincospif(-(float)m * (1.0f / 1024.0f), &sv, &cv);
        tw[m] = make_float2(cv, sv);
    }
    __syncthreads();

    // 11 radix-2 Stockham stages (autosort, natural in/out)
    float2* src = bufA;
    float2* dst = bufB;
    int logNs = 0;
    for (int stage = 0; stage < 11; stage++) {
        const int Ns = 1 << logNs;
        for (int j = tid; j < NHALF / 2; j += 256) {
            float2 v0 = src[j];
            float2 v1 = src[j + NHALF / 2];
            int jm = j & (Ns - 1);
            float2 w = tw[jm << (10 - logNs)];
            float2 v1w = make_float2(w.x * v1.x - w.y * v1.y,
                                     w.x * v1.y + w.y * v1.x);
            int idxD = ((j >> logNs) << (logNs + 1)) | jm;
            dst[idxD]      = make_float2(v0.x + v1w.x, v0.y + v1w.y);
            dst[idxD + Ns] = make_float2(v0.x - v1w.x, v0.y - v1w.y);
        }
        __syncthreads();
        float2* tmp = src; src = dst; dst = tmp;
        logNs++;
    }
    // 11 stages (odd) -> final Z in bufB (== src), bufA (== dst) is free.
    const float2* Z = src;
    float* mag = (float*)dst;                    // overlays free buffer (2048 floats)

    if (tid == 0) mag[0] = 0.0f;
    // untangle real FFT: X[k] = Ae - i*W*Bo, W = e^{-i*pi*k/2048}
    for (int k = tid + 1; k < NHALF; k += 256) {
        float2 zk = Z[k];
        float2 zm = Z[NHALF - k];
        float aex = 0.5f * (zk.x + zm.x), aey = 0.5f * (zk.y - zm.y);
        float box = 0.5f * (zk.x - zm.x), boy = 0.5f * (zk.y + zm.y);
        float sv, cv;
        sincospif(-(float)k * (1.0f / 2048.0f), &sv, &cv);
        float wbx = cv * box - sv * boy;
        float wby = cv * boy + sv * box;
        float Xx = aex + wby;
        float Xy = aey - wbx;
        mag[k] = Xx * Xx + Xy * Xy;
    }
    __syncthreads();

    // top-7 by |X|^2 (monotonic with |X|); lower index wins ties (lax.top_k)
    for (int round = 0; round < KTOP; round++) {
        unsigned long long best = 0ull;
        for (int k = tid; k < NHALF; k += 256) {
            unsigned long long key =
                ((unsigned long long)__float_as_uint(mag[k]) << 32) |
                (unsigned)(2047 - k);
            if (key > best) best = key;
        }
#pragma unroll
        for (int off = 16; off; off >>= 1) {
            unsigned long long o = __shfl_xor_sync(0xffffffffu, best, off);
            if (o > best) best = o;
        }
        if ((tid & 31) == 0) red[tid >> 5] = best;
        __syncthreads();
        if (tid < 8) {
            best = red[tid];
#pragma unroll
            for (int off = 4; off; off >>= 1) {
                unsigned long long o = __shfl_xor_sync(0xffu, best, off);
                if (o > best) best = o;
            }
            if (tid == 0) {
                int kk = 2047 - (int)(best & 0xffffffffu);
                winners[round] = kk;
                mag[kk] = 0.0f;                 // remove from further rounds
            }
        }
        __syncthreads();
    }

    // emit coefficients: amp = 4|X|/T = |X|/1024, phase = atan2
    if (tid < KTOP) {
        int k = winners[tid];
        float2 zk = Z[k];
        float2 zm = Z[NHALF - k];
        float aex = 0.5f * (zk.x + zm.x), aey = 0.5f * (zk.y - zm.y);
        float box = 0.5f * (zk.x - zm.x), boy = 0.5f * (zk.y + zm.y);
        float sv, cv;
        sincospif(-(float)k * (1.0f / 2048.0f), &sv, &cv);
        float wbx = cv * box - sv * boy;
        float wby = cv * boy + sv * box;
        float Xx = aex + wby;
        float Xy = aey - wbx;
        float amp = sqrtf(Xx * Xx + Xy * Xy) * (1.0f / 1024.0f);
        float ph  = atan2f(Xy, Xx);
        g_sel[s * KTOP + tid] = make_float4(amp, ph, (float)k, 0.0f);
    }
}

// ---------------- kernel 3: reconstruction ----------------
// out[b,t,d] = sum_j amp_j * cos(pi*((k_j*t) mod 4096)/2048 + phi_j)
__global__ void __launch_bounds__(256) recon_kernel(float* __restrict__ out) {
    const int d  = threadIdx.x;          // 0..255
    const int tc = blockIdx.x & 255;     // 16-t chunk id
    const int b  = blockIdx.x >> 8;      // 0..15
    const int s  = (b << 8) | d;

    float c[KTOP], ph[KTOP];
    int   k[KTOP];
#pragma unroll
    for (int j = 0; j < KTOP; j++) {
        float4 v = g_sel[s * KTOP + j];
        c[j] = v.x; ph[j] = v.y; k[j] = (int)v.z;
    }

    const int t0 = tc * 16;
    float* op = out + ((size_t)b * TLEN + t0) * 256 + d;
    const float PI_OVER_2048 = 1.5339807878856412e-3f;
#pragma unroll
    for (int i = 0; i < 16; i++) {
        int t = t0 + i;
        float acc = 0.0f;
#pragma unroll
        for (int j = 0; j < KTOP; j++) {
            int r = (k[j] * t) & 4095;               // exact: k*t < 2^24
            acc += c[j] * __cosf(fmaf((float)r, PI_OVER_2048, ph[j]));
        }
        op[(size_t)i * 256] = acc;
    }
}

// ---------------- launch ----------------
extern "C" void kernel_launch(void* const* d_in, const int* in_sizes, int n_in,
                              void* d_out, int out_size) {
    const float* x = (const float*)d_in[0];
    dim3 tb(32, 8);
    dim3 tg(TLEN / 32, 256 / 32, 16);
    transpose_kernel<<<tg, tb>>>(x);
    fft_topk_kernel<<<NSIG, 256>>>();
    recon_kernel<<<NSIG, 256>>>((float*)d_out);
}

// round 7
// speedup vs baseline: 1.6210x; 1.6210x over previous
#include <cuda_runtime.h>
#include <math.h>

// ---------------- device scratch (no allocations allowed) ----------------
__device__ float  g_xt[16u * 256u * 4096u];   // transposed input (b,d,t), 64MB
__device__ float4 g_sel[4096 * 7];            // per-signal: (A, B, k, pad)

#define NSIG   4096
#define TLEN   4096
#define KTOP   7

// padded smem index maps (float2 units)
#define PB(i) ((i) + ((i) >> 3))              // buffer written with stride-8 pattern
#define PA(i) ((i) + (((i) >> 6) << 3))       // buffer written with stride-64 pattern

__device__ __forceinline__ float2 cmul(float2 a, float2 b) {
    return make_float2(fmaf(a.x, b.x, -a.y * b.y), fmaf(a.x, b.y, a.y * b.x));
}
__device__ __forceinline__ float2 cadd(float2 a, float2 b) { return make_float2(a.x + b.x, a.y + b.y); }
__device__ __forceinline__ float2 csub(float2 a, float2 b) { return make_float2(a.x - b.x, a.y - b.y); }

// 8-point DFT (y[p] = sum_r a[r] * e^{-2pi i p r / 8})
__device__ __forceinline__ void dft8(const float2* a, float2* y) {
    const float S = 0.70710678118654752440f;
    float2 e0 = cadd(a[0], a[4]), o0 = csub(a[0], a[4]);
    float2 e1 = cadd(a[1], a[5]), o1 = csub(a[1], a[5]);
    float2 e2 = cadd(a[2], a[6]), o2 = csub(a[2], a[6]);
    float2 e3 = cadd(a[3], a[7]), o3 = csub(a[3], a[7]);
    // even outputs: DFT4 of e
    float2 t0 = cadd(e0, e2), t1 = csub(e0, e2), t2 = cadd(e1, e3), t3 = csub(e1, e3);
    y[0] = cadd(t0, t2);
    y[4] = csub(t0, t2);
    y[2] = make_float2(t1.x + t3.y, t1.y - t3.x);
    y[6] = make_float2(t1.x - t3.y, t1.y + t3.x);
    // odd outputs: DFT4 of o_r * W8^r
    float2 c1 = make_float2(S * (o1.x + o1.y), S * (o1.y - o1.x));     // *e^{-i pi/4}
    float2 c2 = make_float2(o2.y, -o2.x);                              // *(-i)
    float2 c3 = make_float2(S * (o3.y - o3.x), -S * (o3.x + o3.y));    // *e^{-3i pi/4}
    t0 = cadd(o0, c2); t1 = csub(o0, c2); t2 = cadd(c1, c3); t3 = csub(c1, c3);
    y[1] = cadd(t0, t2);
    y[5] = csub(t0, t2);
    y[3] = make_float2(t1.x + t3.y, t1.y - t3.x);
    y[7] = make_float2(t1.x - t3.y, t1.y + t3.x);
}

// ---------------- kernel 1: transpose (b,t,d) -> (b,d,t) ----------------
__global__ void transpose_kernel(const float* __restrict__ in) {
    __shared__ float tile[32][33];
    int b  = blockIdx.z;
    int t0 = blockIdx.x * 32;
    int d0 = blockIdx.y * 32;
    const float* inp = in + (size_t)b * TLEN * 256;
#pragma unroll
    for (int k = 0; k < 4; k++) {
        int tl = threadIdx.y + k * 8;
        tile[tl][threadIdx.x] = inp[(size_t)(t0 + tl) * 256 + d0 + threadIdx.x];
    }
    __syncthreads();
    float* outp = g_xt + (size_t)b * 256 * TLEN;
#pragma unroll
    for (int k = 0; k < 4; k++) {
        int dl = threadIdx.y + k * 8;
        outp[(size_t)(d0 + dl) * TLEN + t0 + threadIdx.x] = tile[threadIdx.x][dl];
    }
}

// ---------------- kernel 2: 2048-pt mixed-radix Stockham FFT + top-7 -----
// stages: radix-8 (Ns=1, global->B), radix-8 (Ns=8, B->A),
//         radix-8 (Ns=64, A->B), radix-4 (Ns=512, B->A)
__global__ void __launch_bounds__(256, 3) fft_topk_kernel() {
    __shared__ float2 sA[2304];      // PA layout
    __shared__ float2 sB[2304];      // PB layout
    __shared__ float2 tw[1024];      // tw[m] = e^{-2 pi i m / 2048}
    __shared__ unsigned long long red[8];
    __shared__ unsigned long long wkey;
    __shared__ int winners[KTOP];

    const int tid = threadIdx.x;
    const int s   = blockIdx.x;

    for (int m = tid; m < 1024; m += 256) {
        float sv, cv;
        sincospif(-(float)m * (1.0f / 1024.0f), &sv, &cv);
        tw[m] = make_float2(cv, sv);
    }

    // ---- stage 0: radix-8, Ns=1, read global (packed z[n]=x[2n]+i x[2n+1])
    {
        const float2* zin = (const float2*)(g_xt + (size_t)s * TLEN);
        float2 a[8];
#pragma unroll
        for (int r = 0; r < 8; r++) a[r] = zin[tid + (r << 8)];
        float2 y[8];
        dft8(a, y);
#pragma unroll
        for (int p = 0; p < 8; p++) sB[PB(8 * tid + p)] = y[p];
    }
    __syncthreads();

#define RADIX8_STAGE(SBUF, SPAD, DBUF, DPAD, NSM1, LOG, STSH)                         \
    do {                                                                              \
        int jm = tid & (NSM1);                                                        \
        float2 a[8];                                                                  \
        _Pragma("unroll")                                                             \
        for (int r = 0; r < 8; r++) a[r] = SBUF[SPAD(tid + (r << 8))];                \
        float2 w1 = tw[jm << (STSH)];                                                 \
        float2 w2 = cmul(w1, w1);                                                     \
        float2 w3 = cmul(w2, w1);                                                     \
        float2 w4 = cmul(w2, w2);                                                     \
        float2 w5 = cmul(w2, w3);                                                     \
        float2 w6 = cmul(w3, w3);                                                     \
        float2 w7 = cmul(w4, w3);                                                     \
        a[1] = cmul(a[1], w1); a[2] = cmul(a[2], w2); a[3] = cmul(a[3], w3);          \
        a[4] = cmul(a[4], w4); a[5] = cmul(a[5], w5); a[6] = cmul(a[6], w6);          \
        a[7] = cmul(a[7], w7);                                                        \
        float2 y[8];                                                                  \
        dft8(a, y);                                                                   \
        int base = ((tid >> (LOG)) << ((LOG) + 3)) | jm;                              \
        _Pragma("unroll")                                                             \
        for (int p = 0; p < 8; p++) DBUF[DPAD(base + (p << (LOG)))] = y[p];           \
    } while (0)

    // ---- stage 1: radix-8, Ns=8 (tw step 32 = <<5)
    RADIX8_STAGE(sB, PB, sA, PA, 7, 3, 5);
    __syncthreads();
    // ---- stage 2: radix-8, Ns=64 (tw step 4 = <<2)
    RADIX8_STAGE(sA, PA, sB, PB, 63, 6, 2);
    __syncthreads();
    // ---- stage 3: radix-4, Ns=512 (tw step 1)
    {
#pragma unroll
        for (int h = 0; h < 2; h++) {
            int j = tid + (h << 8);                 // j in [0, 512)
            float2 b0 = sB[PB(j)];
            float2 b1 = sB[PB(j + 512)];
            float2 b2 = sB[PB(j + 1024)];
            float2 b3 = sB[PB(j + 1536)];
            float2 w1 = tw[j];
            float2 w2 = cmul(w1, w1);
            float2 w3 = cmul(w2, w1);
            b1 = cmul(b1, w1); b2 = cmul(b2, w2); b3 = cmul(b3, w3);
            float2 t0 = cadd(b0, b2), t1 = csub(b0, b2);
            float2 t2 = cadd(b1, b3), t3 = csub(b1, b3);
            sA[PA(j)]        = cadd(t0, t2);
            sA[PA(j + 512)]  = make_float2(t1.x + t3.y, t1.y - t3.x);
            sA[PA(j + 1024)] = csub(t0, t2);
            sA[PA(j + 1536)] = make_float2(t1.x - t3.y, t1.y + t3.x);
        }
    }
    __syncthreads();

    // ---- untangle real FFT, build packed keys in registers
    unsigned long long keys[8];
#pragma unroll
    for (int i = 0; i < 8; i++) {
        int k = tid + 1 + (i << 8);
        keys[i] = 0ull;
        if (k < 2048) {
            float2 zk = sA[PA(k)];
            float2 zm = sA[PA(2048 - k)];
            float aex = 0.5f * (zk.x + zm.x), aey = 0.5f * (zk.y - zm.y);
            float box = 0.5f * (zk.x - zm.x), boy = 0.5f * (zk.y + zm.y);
            float sv, cv;
            sincospif(-(float)k * (1.0f / 2048.0f), &sv, &cv);
            float wbx = cv * box - sv * boy;
            float wby = cv * boy + sv * box;
            float Xx = aex + wby;
            float Xy = aey - wbx;
            float mag = Xx * Xx + Xy * Xy;
            keys[i] = ((unsigned long long)__float_as_uint(mag) << 32) |
                      (unsigned)(2047 - k);       // tie-break: lower k wins
        }
    }

    // ---- 7 rounds of block argmax over register keys
    for (int round = 0; round < KTOP; round++) {
        unsigned long long best = keys[0];
#pragma unroll
        for (int i = 1; i < 8; i++) if (keys[i] > best) best = keys[i];
#pragma unroll
        for (int off = 16; off; off >>= 1) {
            unsigned long long o = __shfl_xor_sync(0xffffffffu, best, off);
            if (o > best) best = o;
        }
        if ((tid & 31) == 0) red[tid >> 5] = best;
        __syncthreads();
        if (tid < 8) {
            best = red[tid];
#pragma unroll
            for (int off = 4; off; off >>= 1) {
                unsigned long long o = __shfl_xor_sync(0xffu, best, off);
                if (o > best) best = o;
            }
            if (tid == 0) {
                wkey = best;
                winners[round] = 2047 - (int)(best & 0xffffffffu);
            }
        }
        __syncthreads();
        unsigned long long w = wkey;
#pragma unroll
        for (int i = 0; i < 8; i++) if (keys[i] == w) keys[i] = 0ull;
    }

    // ---- emit (A, B, k): term_t = A cos(wt) + B sin(wt), A=Re/1024, B=-Im/1024
    if (tid < KTOP) {
        int k = winners[tid];
        float2 zk = sA[PA(k)];
        float2 zm = sA[PA(2048 - k)];
        float aex = 0.5f * (zk.x + zm.x), aey = 0.5f * (zk.y - zm.y);
        float box = 0.5f * (zk.x - zm.x), boy = 0.5f * (zk.y + zm.y);
        float sv, cv;
        sincospif(-(float)k * (1.0f / 2048.0f), &sv, &cv);
        float wbx = cv * box - sv * boy;
        float wby = cv * boy + sv * box;
        float Xx = aex + wby;
        float Xy = aey - wbx;
        g_sel[s * KTOP + tid] =
            make_float4(Xx * (1.0f / 1024.0f), -Xy * (1.0f / 1024.0f), (float)k, 0.0f);
    }
}

// ---------------- kernel 3: reconstruction via Chebyshev recurrence ------
// u_t = A cos(wt) + B sin(wt);  u_{t+1} = 2cos(d) u_t - u_{t-1}, d = pi k/2048
__global__ void __launch_bounds__(256) recon_kernel(float* __restrict__ out) {
    const int d  = threadIdx.x;
    const int tc = blockIdx.x & 127;
    const int b  = blockIdx.x >> 7;
    const int s  = (b << 8) | d;
    const int t0 = tc << 5;                       // 32 t per thread

    float u0[KTOP], u1[KTOP], m2[KTOP];
    float s0 = 0.0f, s1 = 0.0f;
#pragma unroll
    for (int j = 0; j < KTOP; j++) {
        float4 v = g_sel[s * KTOP + j];
        float A = v.x, B = v.y;
        int   k = (int)v.z;
        float sd, cd;
        sincospif((float)k * (1.0f / 2048.0f), &sd, &cd);      // sin/cos(delta)
        int r0 = (k * t0) & 4095;                               // exact
        float sth, cth;
        sincospif((float)r0 * (1.0f / 2048.0f), &sth, &cth);   // sin/cos(w*t0)
        float a0 = fmaf(A, cth, B * sth);
        float c1 = fmaf(cth, cd, -sth * sd);                    // cos(w*(t0+1))
        float s1t = fmaf(sth, cd, cth * sd);                    // sin(w*(t0+1))
        float a1 = fmaf(A, c1, B * s1t);
        u0[j] = a0; u1[j] = a1; m2[j] = 2.0f * cd;
        s0 += a0; s1 += a1;
    }

    float* op = out + ((size_t)((b << 12) | t0)) * 256 + d;
    op[0]   = s0;
    op[256] = s1;
#pragma unroll
    for (int i = 2; i < 32; i++) {
        float acc = 0.0f;
#pragma unroll
        for (int j = 0; j < KTOP; j++) {
            float u2 = fmaf(m2[j], u1[j], -u0[j]);
            u0[j] = u1[j];
            u1[j] = u2;
            acc += u2;
        }
        op[(size_t)i * 256] = acc;
    }
}

// ---------------- launch ----------------
extern "C" void kernel_launch(void* const* d_in, const int* in_sizes, int n_in,
                              void* d_out, int out_size) {
    const float* x = (const float*)d_in[0];
    dim3 tb(32, 8);
    dim3 tg(TLEN / 32, 256 / 32, 16);
    transpose_kernel<<<tg, tb>>>(x);
    fft_topk_kernel<<<NSIG, 256>>>();
    recon_kernel<<<16 * 128, 256>>>((float*)d_out);
}

// round 8
// speedup vs baseline: 1.8233x; 1.1248x over previous
#include <cuda_runtime.h>
#include <math.h>

// ---------------- device scratch (no allocations allowed) ----------------
__device__ float  g_xt[16u * 256u * 4096u];   // transposed input (b,d,t), 64MB
__device__ float4 g_sel[4096 * 7];            // per-signal: (A, B, k, pad)

#define NSIG   4096
#define TLEN   4096
#define KTOP   7

// padded smem index maps (float2 units)
#define PB(i) ((i) + ((i) >> 3))              // buffer written with stride-8 pattern
#define PA(i) ((i) + (((i) >> 6) << 3))       // buffer written with stride-64 pattern

__device__ __forceinline__ float2 cmul(float2 a, float2 b) {
    return make_float2(fmaf(a.x, b.x, -a.y * b.y), fmaf(a.x, b.y, a.y * b.x));
}
__device__ __forceinline__ float2 cadd(float2 a, float2 b) { return make_float2(a.x + b.x, a.y + b.y); }
__device__ __forceinline__ float2 csub(float2 a, float2 b) { return make_float2(a.x - b.x, a.y - b.y); }

// 8-point DFT (y[p] = sum_r a[r] * e^{-2pi i p r / 8})
__device__ __forceinline__ void dft8(const float2* a, float2* y) {
    const float S = 0.70710678118654752440f;
    float2 e0 = cadd(a[0], a[4]), o0 = csub(a[0], a[4]);
    float2 e1 = cadd(a[1], a[5]), o1 = csub(a[1], a[5]);
    float2 e2 = cadd(a[2], a[6]), o2 = csub(a[2], a[6]);
    float2 e3 = cadd(a[3], a[7]), o3 = csub(a[3], a[7]);
    float2 t0 = cadd(e0, e2), t1 = csub(e0, e2), t2 = cadd(e1, e3), t3 = csub(e1, e3);
    y[0] = cadd(t0, t2);
    y[4] = csub(t0, t2);
    y[2] = make_float2(t1.x + t3.y, t1.y - t3.x);
    y[6] = make_float2(t1.x - t3.y, t1.y + t3.x);
    float2 c1 = make_float2(S * (o1.x + o1.y), S * (o1.y - o1.x));
    float2 c2 = make_float2(o2.y, -o2.x);
    float2 c3 = make_float2(S * (o3.y - o3.x), -S * (o3.x + o3.y));
    t0 = cadd(o0, c2); t1 = csub(o0, c2); t2 = cadd(c1, c3); t3 = csub(c1, c3);
    y[1] = cadd(t0, t2);
    y[5] = csub(t0, t2);
    y[3] = make_float2(t1.x + t3.y, t1.y - t3.x);
    y[7] = make_float2(t1.x - t3.y, t1.y + t3.x);
}

// ---------------- kernel 1: transpose (b,t,d) -> (b,d,t), float4 I/O -----
__global__ void __launch_bounds__(256) transpose_kernel(const float* __restrict__ in) {
    __shared__ float tile[32][33];
    const int b  = blockIdx.z;
    const int t0 = blockIdx.x * 32;
    const int d0 = blockIdx.y * 32;
    const int i  = threadIdx.x;

    // load: 32 t-rows x 32 d, one float4 along d per thread
    {
        const int row = i >> 3, c4 = (i & 7) << 2;
        float4 v = *(const float4*)(in + ((size_t)b * TLEN + t0 + row) * 256 + d0 + c4);
        tile[row][c4 + 0] = v.x;
        tile[row][c4 + 1] = v.y;
        tile[row][c4 + 2] = v.z;
        tile[row][c4 + 3] = v.w;
    }
    __syncthreads();
    // store: 32 d-rows x 32 t, one float4 along t per thread
    {
        const int drow = i >> 3, tc = (i & 7) << 2;
        float4 w;
        w.x = tile[tc + 0][drow];
        w.y = tile[tc + 1][drow];
        w.z = tile[tc + 2][drow];
        w.w = tile[tc + 3][drow];
        *(float4*)(g_xt + ((size_t)b * 256 + d0 + drow) * TLEN + t0 + tc) = w;
    }
}

// ---------------- kernel 2: 2048-pt mixed-radix Stockham FFT + top-7 -----
__global__ void __launch_bounds__(256, 4) fft_topk_kernel() {
    __shared__ float2 sA[2304];      // PA layout
    __shared__ float2 sB[2304];      // PB layout
    __shared__ float2 tw[1024];      // tw[m] = e^{-i pi m / 1024}
    __shared__ unsigned long long red[8];
    __shared__ unsigned long long wkey;
    __shared__ int winners[KTOP];

    const int tid = threadIdx.x;
    const int s   = blockIdx.x;

    // twiddles: 2 sincospif per thread; tw[m+512] = tw[m] * (-i)
    for (int m = tid; m < 512; m += 256) {
        float sv, cv;
        sincospif(-(float)m * (1.0f / 1024.0f), &sv, &cv);
        tw[m]       = make_float2(cv, sv);
        tw[m + 512] = make_float2(sv, -cv);
    }

    // ---- stage 0: radix-8, Ns=1, read global (packed z[n]=x[2n]+i x[2n+1])
    {
        const float2* zin = (const float2*)(g_xt + (size_t)s * TLEN);
        float2 a[8];
#pragma unroll
        for (int r = 0; r < 8; r++) a[r] = zin[tid + (r << 8)];
        float2 y[8];
        dft8(a, y);
#pragma unroll
        for (int p = 0; p < 8; p++) sB[PB(8 * tid + p)] = y[p];
    }
    __syncthreads();

#define RADIX8_STAGE(SBUF, SPAD, DBUF, DPAD, NSM1, LOG, STSH)                         \
    do {                                                                              \
        int jm = tid & (NSM1);                                                        \
        float2 a[8];                                                                  \
        _Pragma("unroll")                                                             \
        for (int r = 0; r < 8; r++) a[r] = SBUF[SPAD(tid + (r << 8))];                \
        float2 w1 = tw[jm << (STSH)];                                                 \
        float2 w2 = cmul(w1, w1);                                                     \
        float2 w3 = cmul(w2, w1);                                                     \
        float2 w4 = cmul(w2, w2);                                                     \
        float2 w5 = cmul(w2, w3);                                                     \
        float2 w6 = cmul(w3, w3);                                                     \
        float2 w7 = cmul(w4, w3);                                                     \
        a[1] = cmul(a[1], w1); a[2] = cmul(a[2], w2); a[3] = cmul(a[3], w3);          \
        a[4] = cmul(a[4], w4); a[5] = cmul(a[5], w5); a[6] = cmul(a[6], w6);          \
        a[7] = cmul(a[7], w7);                                                        \
        float2 y[8];                                                                  \
        dft8(a, y);                                                                   \
        int base = ((tid >> (LOG)) << ((LOG) + 3)) | jm;                              \
        _Pragma("unroll")                                                             \
        for (int p = 0; p < 8; p++) DBUF[DPAD(base + (p << (LOG)))] = y[p];           \
    } while (0)

    // ---- stage 1: radix-8, Ns=8 (tw step <<5)
    RADIX8_STAGE(sB, PB, sA, PA, 7, 3, 5);
    __syncthreads();
    // ---- stage 2: radix-8, Ns=64 (tw step <<2)
    RADIX8_STAGE(sA, PA, sB, PB, 63, 6, 2);
    __syncthreads();
    // ---- stage 3: radix-4, Ns=512 (tw step 1)
    {
#pragma unroll
        for (int h = 0; h < 2; h++) {
            int j = tid + (h << 8);
            float2 b0 = sB[PB(j)];
            float2 b1 = sB[PB(j + 512)];
            float2 b2 = sB[PB(j + 1024)];
            float2 b3 = sB[PB(j + 1536)];
            float2 w1 = tw[j];
            float2 w2 = cmul(w1, w1);
            float2 w3 = cmul(w2, w1);
            b1 = cmul(b1, w1); b2 = cmul(b2, w2); b3 = cmul(b3, w3);
            float2 t0 = cadd(b0, b2), t1 = csub(b0, b2);
            float2 t2 = cadd(b1, b3), t3 = csub(b1, b3);
            sA[PA(j)]        = cadd(t0, t2);
            sA[PA(j + 512)]  = make_float2(t1.x + t3.y, t1.y - t3.x);
            sA[PA(j + 1024)] = csub(t0, t2);
            sA[PA(j + 1536)] = make_float2(t1.x - t3.y, t1.y + t3.x);
        }
    }
    __syncthreads();

    // untangle twiddle e^{-i pi k/2048}: even k -> tw[k/2], odd k -> tw[k>>1]*C
    const float2 C = make_float2(0.99999882345170f, -0.00153398018625f);

    // ---- untangle real FFT, build packed keys in registers
    unsigned long long keys[8];
#pragma unroll
    for (int i = 0; i < 8; i++) {
        int k = tid + 1 + (i << 8);
        keys[i] = 0ull;
        if (k < 2048) {
            float2 zk = sA[PA(k)];
            float2 zm = sA[PA(2048 - k)];
            float aex = 0.5f * (zk.x + zm.x), aey = 0.5f * (zk.y - zm.y);
            float box = 0.5f * (zk.x - zm.x), boy = 0.5f * (zk.y + zm.y);
            float2 w = tw[k >> 1];
            if (k & 1) w = cmul(w, C);
            float wbx = w.x * box - w.y * boy;
            float wby = w.x * boy + w.y * box;
            float Xx = aex + wby;
            float Xy = aey - wbx;
            float mag = Xx * Xx + Xy * Xy;
            keys[i] = ((unsigned long long)__float_as_uint(mag) << 32) |
                      (unsigned)(2047 - k);       // tie-break: lower k wins
        }
    }

    // ---- 7 rounds of block argmax over register keys
    for (int round = 0; round < KTOP; round++) {
        unsigned long long best = keys[0];
#pragma unroll
        for (int i = 1; i < 8; i++) if (keys[i] > best) best = keys[i];
#pragma unroll
        for (int off = 16; off; off >>= 1) {
            unsigned long long o = __shfl_xor_sync(0xffffffffu, best, off);
            if (o > best) best = o;
        }
        if ((tid & 31) == 0) red[tid >> 5] = best;
        __syncthreads();
        if (tid < 8) {
            best = red[tid];
#pragma unroll
            for (int off = 4; off; off >>= 1) {
                unsigned long long o = __shfl_xor_sync(0xffu, best, off);
                if (o > best) best = o;
            }
            if (tid == 0) {
                wkey = best;
                winners[round] = 2047 - (int)(best & 0xffffffffu);
            }
        }
        __syncthreads();
        unsigned long long w = wkey;
#pragma unroll
        for (int i = 0; i < 8; i++) if (keys[i] == w) keys[i] = 0ull;
    }

    // ---- emit (A, B, k): term_t = A cos(wt) + B sin(wt), A=Re/1024, B=-Im/1024
    if (tid < KTOP) {
        int k = winners[tid];
        float2 zk = sA[PA(k)];
        float2 zm = sA[PA(2048 - k)];
        float aex = 0.5f * (zk.x + zm.x), aey = 0.5f * (zk.y - zm.y);
        float box = 0.5f * (zk.x - zm.x), boy = 0.5f * (zk.y + zm.y);
        float2 w = tw[k >> 1];
        if (k & 1) w = cmul(w, C);
        float wbx = w.x * box - w.y * boy;
        float wby = w.x * boy + w.y * box;
        float Xx = aex + wby;
        float Xy = aey - wbx;
        g_sel[s * KTOP + tid] =
            make_float4(Xx * (1.0f / 1024.0f), -Xy * (1.0f / 1024.0f), (float)k, 0.0f);
    }
}

// ---------------- kernel 3: reconstruction via Chebyshev recurrence ------
// u_t = A cos(wt) + B sin(wt);  u_{t+1} = 2cos(d) u_t - u_{t-1}, d = pi k/2048
__global__ void __launch_bounds__(256) recon_kernel(float* __restrict__ out) {
    const int d  = threadIdx.x;
    const int tc = blockIdx.x & 63;
    const int b  = blockIdx.x >> 6;
    const int s  = (b << 8) | d;
    const int t0 = tc << 6;                       // 64 t per thread

    float u0[KTOP], u1[KTOP], m2[KTOP];
    float s0 = 0.0f, s1 = 0.0f;
#pragma unroll
    for (int j = 0; j < KTOP; j++) {
        float4 v = g_sel[s * KTOP + j];
        float A = v.x, B = v.y;
        int   k = (int)v.z;
        float sd, cd;
        sincospif((float)k * (1.0f / 2048.0f), &sd, &cd);      // sin/cos(delta)
        int r0 = (k * t0) & 4095;                               // exact
        float sth, cth;
        sincospif((float)r0 * (1.0f / 2048.0f), &sth, &cth);   // sin/cos(w*t0)
        float a0 = fmaf(A, cth, B * sth);
        float c1 = fmaf(cth, cd, -sth * sd);                    // cos(w*(t0+1))
        float s1t = fmaf(sth, cd, cth * sd);                    // sin(w*(t0+1))
        float a1 = fmaf(A, c1, B * s1t);
        u0[j] = a0; u1[j] = a1; m2[j] = 2.0f * cd;
        s0 += a0; s1 += a1;
    }

    float* op = out + ((size_t)((b << 12) | t0)) * 256 + d;
    op[0]   = s0;
    op[256] = s1;
#pragma unroll
    for (int i = 2; i < 64; i++) {
        float acc = 0.0f;
#pragma unroll
        for (int j = 0; j < KTOP; j++) {
            float u2 = fmaf(m2[j], u1[j], -u0[j]);
            u0[j] = u1[j];
            u1[j] = u2;
            acc += u2;
        }
        op[(size_t)i * 256] = acc;
    }
}

// ---------------- launch ----------------
extern "C" void kernel_launch(void* const* d_in, const int* in_sizes, int n_in,
                              void* d_out, int out_size) {
    const float* x = (const float*)d_in[0];
    transpose_kernel<<<dim3(TLEN / 32, 256 / 32, 16), 256>>>(x);
    fft_topk_kernel<<<NSIG, 256>>>();
    recon_kernel<<<16 * 64, 256>>>((float*)d_out);
}